// round 7
// baseline (speedup 1.0000x reference)
#include <cuda_runtime.h>

// out[b,m] = dot(inputs[b,m,:], W[m,:]) + bias[m]
// B=1024, M=2048, I=128 (fp32). Purely HBM-bound: 1.082 GB compulsory traffic.
// R1 shape (4 rows/warp, high occupancy) + __ldcs streaming loads on x +
// one coalesced 16B store per warp. Chip-wide outstanding loads = occ x MLP
// is what feeds DRAM: keep regs low, occupancy high.

constexpr int B_DIM = 1024;
constexpr int M_DIM = 2048;
constexpr int I_DIM = 128;                  // 32 float4 per row
constexpr int ROWS_PER_WARP = 4;
constexpr int THREADS = 256;                // 8 warps/block
constexpr long long TOTAL_ROWS = (long long)B_DIM * M_DIM;        // 2,097,152
constexpr int ROWS_PER_BLOCK = ROWS_PER_WARP * (THREADS / 32);    // 32
constexpr int GRID = (int)(TOTAL_ROWS / ROWS_PER_BLOCK);          // 65,536

__global__ __launch_bounds__(THREADS)
void diag_linear_kernel(const float4* __restrict__ x,     // [B*M, 32] float4
                        const float4* __restrict__ w,     // [M, 32] float4
                        const float*  __restrict__ bias,  // [M]
                        float*        __restrict__ out)   // [B*M]
{
    const int lane = threadIdx.x & 31;
    const int warp_in_block = threadIdx.x >> 5;
    const long long warp_global = (long long)blockIdx.x * (THREADS / 32) + warp_in_block;
    const long long row0 = warp_global * ROWS_PER_WARP;

    // Front-batch the 4 DRAM loads (independent LDG.128 with evict-first).
    float4 a[ROWS_PER_WARP];
#pragma unroll
    for (int r = 0; r < ROWS_PER_WARP; r++) {
        a[r] = __ldcs(&x[(row0 + r) * (I_DIM / 4) + lane]);
    }

    // W rows: L2-resident (1 MB total, reused 1024x).
    float4 ww[ROWS_PER_WARP];
#pragma unroll
    for (int r = 0; r < ROWS_PER_WARP; r++) {
        const int m = (int)((row0 + r) & (M_DIM - 1));
        ww[r] = __ldg(&w[(long long)m * (I_DIM / 4) + lane]);
    }

    float keep = 0.0f;
#pragma unroll
    for (int r = 0; r < ROWS_PER_WARP; r++) {
        float s = fmaf(a[r].x, ww[r].x,
                  fmaf(a[r].y, ww[r].y,
                  fmaf(a[r].z, ww[r].z,
                       a[r].w * ww[r].w)));
#pragma unroll
        for (int off = 16; off; off >>= 1)
            s += __shfl_xor_sync(0xffffffffu, s, off);
        if (lane == r) keep = s;   // park row r's sum on lane r
    }

    // One coalesced 16B store per warp (lanes 0..3), bias added here.
    if (lane < ROWS_PER_WARP) {
        const long long row = row0 + lane;
        const int m = (int)(row & (M_DIM - 1));
        out[row] = keep + __ldg(&bias[m]);
    }
}

extern "C" void kernel_launch(void* const* d_in, const int* in_sizes, int n_in,
                              void* d_out, int out_size)
{
    const float4* x    = (const float4*)d_in[0];  // inputs  [B, M, I]
    const float4* w    = (const float4*)d_in[1];  // Rk_weight [M, I]
    const float*  bias = (const float*)d_in[2];   // bias [M]
    float* out = (float*)d_out;                   // [B, M]

    diag_linear_kernel<<<GRID, THREADS>>>(x, w, bias, out);
}

// round 9
// speedup vs baseline: 1.0064x; 1.0064x over previous
#include <cuda_runtime.h>

// out[b,m] = dot(inputs[b,m,:], W[m,:]) + bias[m]
// B=1024, M=2048, I=128 (fp32). Purely HBM-bound: 1.086 GB compulsory traffic.
// R1 shape restored: 4 rows/warp, plain LDG.128 loads, 5-step butterfly.
// __launch_bounds__(256,8) pins regs <= 32 (occupancy 2048 thr/SM).
// Lane 0 emits ONE STG.128 per warp instead of 4x STG.32.

constexpr int B_DIM = 1024;
constexpr int M_DIM = 2048;
constexpr int I_DIM = 128;                  // 32 float4 per row
constexpr int ROWS_PER_WARP = 4;
constexpr int THREADS = 256;                // 8 warps/block
constexpr long long TOTAL_ROWS = (long long)B_DIM * M_DIM;        // 2,097,152
constexpr int ROWS_PER_BLOCK = ROWS_PER_WARP * (THREADS / 32);    // 32
constexpr int GRID = (int)(TOTAL_ROWS / ROWS_PER_BLOCK);          // 65,536

__global__ __launch_bounds__(THREADS, 8)
void diag_linear_kernel(const float4* __restrict__ x,     // [B*M, 32] float4
                        const float4* __restrict__ w,     // [M, 32] float4
                        const float*  __restrict__ bias,  // [M]
                        float4*       __restrict__ out)   // [B*M/4] float4
{
    const int lane = threadIdx.x & 31;
    const int warp_in_block = threadIdx.x >> 5;
    const long long warp_global = (long long)blockIdx.x * (THREADS / 32) + warp_in_block;
    const long long row0 = warp_global * ROWS_PER_WARP;

    // Front-batch all global loads (8 independent LDG.128 in flight).
    float4 a[ROWS_PER_WARP];
#pragma unroll
    for (int r = 0; r < ROWS_PER_WARP; r++) {
        a[r] = x[(row0 + r) * (I_DIM / 4) + lane];
    }
    float4 ww[ROWS_PER_WARP];
#pragma unroll
    for (int r = 0; r < ROWS_PER_WARP; r++) {
        const int m = (int)((row0 + r) & (M_DIM - 1));
        ww[r] = w[(long long)m * (I_DIM / 4) + lane];
    }

    float4 res;
    float* res_f = (float*)&res;
#pragma unroll
    for (int r = 0; r < ROWS_PER_WARP; r++) {
        float s = fmaf(a[r].x, ww[r].x,
                  fmaf(a[r].y, ww[r].y,
                  fmaf(a[r].z, ww[r].z,
                       a[r].w * ww[r].w)));
#pragma unroll
        for (int off = 16; off; off >>= 1)
            s += __shfl_xor_sync(0xffffffffu, s, off);

        if (lane == 0) {
            const int m = (int)((row0 + r) & (M_DIM - 1));
            res_f[r] = s + __ldg(&bias[m]);
        }
    }

    // Single 16B store per warp (row0 is a multiple of 4).
    if (lane == 0) {
        out[row0 >> 2] = res;
    }
}

extern "C" void kernel_launch(void* const* d_in, const int* in_sizes, int n_in,
                              void* d_out, int out_size)
{
    const float4* x    = (const float4*)d_in[0];  // inputs  [B, M, I]
    const float4* w    = (const float4*)d_in[1];  // Rk_weight [M, I]
    const float*  bias = (const float*)d_in[2];   // bias [M]
    float4* out = (float4*)d_out;                 // [B, M] viewed as float4

    diag_linear_kernel<<<GRID, THREADS>>>(x, w, bias, out);
}

// round 12
// speedup vs baseline: 1.0469x; 1.0403x over previous
#include <cuda_runtime.h>

// out[b,m] = dot(inputs[b,m,:], W[m,:]) + bias[m]
// B=1024, M=2048, I=128 (fp32). Compulsory traffic 1.086 GB -> HBM-bound.
//
// Work mapping: one warp = (fixed m, batches b0..b0+3). One W-row load serves
// 4 x-rows (W L2 traffic cut 4x, LSU ops cut ~45%). Consecutive warps in a
// block share the b-group and take consecutive m, so per-b x reads are a
// contiguous 4KB block and the 8 output floats land in one 32B sector.
// 4-row reduction done with 6 shuffles (row-select tree + butterfly).

constexpr int B_DIM = 1024;
constexpr int M_DIM = 2048;
constexpr int IV    = 128 / 4;              // 32 float4 per row
constexpr int B_PER_WARP = 4;
constexpr int THREADS = 256;                // 8 warps/block
// total warps = M_DIM * (B_DIM / B_PER_WARP) = 2048 * 256 = 524288
constexpr int GRID = (M_DIM * (B_DIM / B_PER_WARP)) / (THREADS / 32);  // 65536

__global__ __launch_bounds__(THREADS, 8)
void diag_linear_kernel(const float4* __restrict__ x,     // [B*M, 32] float4
                        const float4* __restrict__ w,     // [M, 32] float4
                        const float*  __restrict__ bias,  // [M]
                        float*        __restrict__ out)   // [B*M]
{
    const int lane = threadIdx.x & 31;
    const int warp_in_block = threadIdx.x >> 5;
    const unsigned warp_global = blockIdx.x * (THREADS / 32) + warp_in_block;

    const int m    = (int)(warp_global & (M_DIM - 1));       // low bits: consecutive m per block
    const int bgrp = (int)(warp_global >> 11);               // 0..255
    const int b0   = bgrp * B_PER_WARP;

    // 4 independent x-row loads (DRAM) + 1 W-row load (L2). MLP_p1 = 5.
    float4 a[B_PER_WARP];
#pragma unroll
    for (int r = 0; r < B_PER_WARP; r++) {
        a[r] = x[((long long)(b0 + r) * M_DIM + m) * IV + lane];
    }
    const float4 wv = w[(long long)m * IV + lane];
    const float  bv = __ldg(&bias[m]);

    float s[B_PER_WARP];
#pragma unroll
    for (int r = 0; r < B_PER_WARP; r++) {
        s[r] = fmaf(a[r].x, wv.x,
               fmaf(a[r].y, wv.y,
               fmaf(a[r].z, wv.z,
                    a[r].w * wv.w)));
    }

    // 6-shuffle 4-row reduction.
    // Level 16: rows {0,1} and {2,3} folded; bit16 selects which row a lane keeps.
    const bool hi16 = (lane & 16) != 0;
    float c01 = (hi16 ? s[1] : s[0]) + __shfl_xor_sync(0xffffffffu, hi16 ? s[0] : s[1], 16);
    float c23 = (hi16 ? s[3] : s[2]) + __shfl_xor_sync(0xffffffffu, hi16 ? s[2] : s[3], 16);
    // Level 8: fold c01/c23; bit8 selects row pair.
    const bool hi8 = (lane & 8) != 0;
    float c = (hi8 ? c23 : c01) + __shfl_xor_sync(0xffffffffu, hi8 ? c01 : c23, 8);
    // Butterfly over remaining dims 4,2,1.
    c += __shfl_xor_sync(0xffffffffu, c, 4);
    c += __shfl_xor_sync(0xffffffffu, c, 2);
    c += __shfl_xor_sync(0xffffffffu, c, 1);

    // Lane 0 -> row0, lane 16 -> row1, lane 8 -> row2, lane 24 -> row3.
    if ((lane & 7) == 0) {
        const int r = ((lane >> 4) & 1) | ((lane >> 2) & 2);
        out[(long long)(b0 + r) * M_DIM + m] = c + bv;
    }
}

extern "C" void kernel_launch(void* const* d_in, const int* in_sizes, int n_in,
                              void* d_out, int out_size)
{
    const float4* x    = (const float4*)d_in[0];  // inputs  [B, M, I]
    const float4* w    = (const float4*)d_in[1];  // Rk_weight [M, I]
    const float*  bias = (const float*)d_in[2];   // bias [M]
    float* out = (float*)d_out;                   // [B, M]

    diag_linear_kernel<<<GRID, THREADS>>>(x, w, bias, out);
}